// round 9
// baseline (speedup 1.0000x reference)
#include <cuda_runtime.h>

#define Fn 640
#define Vn 322
#define EPSf 1e-8f
#define HALF_BIGf 5e9f
#define FOCALf 3.73205080756887729f
#define NTILE 1024           // 32x32 tiles of 8x8 pixels
#define NTHR 256             // 64 pixels * 4 threads/pixel

// -------- device-global scratch (zero-init; counter monotonic -> graph-safe) ----
__device__ double g_partial[NTILE];
__device__ unsigned int g_rcount;    // monotonic, check (old & 1023) == 1023

__device__ __forceinline__ float tanh_mufu(float x) {
    float y;
    asm("tanh.approx.f32 %0, %1;" : "=f"(y) : "f"(x));
    return y;
}

__global__ void __launch_bounds__(NTHR) fused_kernel(const float* __restrict__ verts,
                                                     const int*   __restrict__ faces,
                                                     const float* __restrict__ tex,
                                                     const float* __restrict__ ref,
                                                     const float* __restrict__ angle,
                                                     float* __restrict__ out) {
    __shared__ float  sx[Vn], sy[Vn], sd[Vn];
    __shared__ float4 sA[Fn];            // w0x w0y w0c w1x
    __shared__ float4 sB[Fn];            // w1y w1c zx  zy
    __shared__ float2 sZF[Fn];           // zc, fid-bits
    __shared__ int sn;
    __shared__ double ss[8];
    __shared__ int sflag;

    int b = blockIdx.x, tid = threadIdx.x;
    int tx = b & 31, ty = b >> 5;

    if (tid == 0) sn = 0;
    // ---- vertex transform (all verts; MUFU sincos) ----
    float th = angle[0] * 6.28318530717958647692f;
    float c = __cosf(th), s = __sinf(th);
    for (int v = tid; v < Vn; v += NTHR) {
        float x = verts[3 * v], y = verts[3 * v + 1], z = verts[3 * v + 2];
        float xr = c * x + s * z;
        float zr = -s * x + c * z;
        float depth = 2.732f - zr;
        float invd = 1.0f / depth;
        sx[v] = FOCALf * xr * invd;
        sy[v] = FOCALf * y * invd;
        sd[v] = depth;
    }
    __syncthreads();

    // ---- prep + SAT cull vs this 8x8 tile + shared-counter compaction ----
    float cxt = (float)(tx * 8 + 4) / 128.0f - 1.0f;
    float cyt = 1.0f - (float)(ty * 8 + 4) / 128.0f;
    const float hext = 3.5f / 128.0f;
    float txmin = (float)(tx * 8) / 128.0f + 0.5f / 128.0f - 1.0f;
    float txmax = txmin + 7.0f / 128.0f;
    float tymax = 1.0f - ((float)(ty * 8) / 128.0f + 0.5f / 128.0f);
    float tymin = tymax - 7.0f / 128.0f;

    for (int f = tid; f < Fn; f += NTHR) {
        int i0 = __ldg(faces + 3 * f), i1 = __ldg(faces + 3 * f + 1), i2 = __ldg(faces + 3 * f + 2);
        float ax = sx[i0], ay = sy[i0];
        float bx = sx[i1], by = sy[i1];
        float cx = sx[i2], cy = sy[i2];
        float area = (bx - ax) * (cy - ay) - (by - ay) * (cx - ax);
        bool valid = fabsf(area) > EPSf;            // NaN -> invalid, matches jnp
        float inv = 1.0f / (valid ? area : 1.0f);
        float e0x = cx - bx, e0y = cy - by;
        float w0x = -e0y * inv, w0y = e0x * inv, w0c = (e0y * bx - e0x * by) * inv;
        float e1x = ax - cx, e1y = ay - cy;
        float w1x = -e1y * inv, w1y = e1x * inv, w1c = (e1y * cx - e1x * cy) * inv;
        if (!valid) { w0x = 0.f; w0y = 0.f; w0c = -1e30f; w1x = 0.f; w1y = 0.f; w1c = 0.f; }
        float w2x = -(w0x + w1x), w2y = -(w0y + w1y), w2c = 1.0f - w0c - w1c;
        // dilated edge half-planes (max over tile pixel box >= -tol)
        float v0 = fmaf(w0x, cxt, fmaf(w0y, cyt, w0c));
        float m0 = (fabsf(w0x) + fabsf(w0y)) * hext
                 + 1e-5f * (fabsf(w0x) + fabsf(w0y) + fabsf(w0c));
        float v1 = fmaf(w1x, cxt, fmaf(w1y, cyt, w1c));
        float m1 = (fabsf(w1x) + fabsf(w1y)) * hext
                 + 1e-5f * (fabsf(w1x) + fabsf(w1y) + fabsf(w1c));
        float v2 = fmaf(w2x, cxt, fmaf(w2y, cyt, w2c));
        float m2 = (fabsf(w2x) + fabsf(w2y)) * hext
                 + 1e-5f * (fabsf(w2x) + fabsf(w2y) + fabsf(w2c));
        bool pass = (v0 + m0 >= 0.f) & (v1 + m1 >= 0.f) & (v2 + m2 >= 0.f);
        // triangle bbox vs tile bbox (caps skinny-triangle miter spikes)
        float bxmin = fminf(ax, fminf(bx, cx)), bxmax = fmaxf(ax, fmaxf(bx, cx));
        float bymin = fminf(ay, fminf(by, cy)), bymax = fmaxf(ay, fmaxf(by, cy));
        pass = pass & (bxmax >= txmin - 1e-4f) & (bxmin <= txmax + 1e-4f)
                    & (bymax >= tymin - 1e-4f) & (bymin <= tymax + 1e-4f);
        if (pass) {
            int slot = atomicAdd(&sn, 1);            // unordered: key-min is order-independent
            float d0 = sd[i0], d1 = sd[i1], d2 = sd[i2];
            float e02 = d0 - d2, e12 = d1 - d2;
            float zx = w0x * e02 + w1x * e12;
            float zy = w0y * e02 + w1y * e12;
            float zc = d2 + w0c * e02 + w1c * e12;
            sA[slot]  = make_float4(w0x, w0y, w0c, w1x);
            sB[slot]  = make_float4(w1y, w1c, zx, zy);
            sZF[slot] = make_float2(zc, __uint_as_float((unsigned)f));
        }
    }
    __syncthreads();
    int n = sn;

    // ---- raster: 4 threads/pixel, strided quarter of the list each ----
    int seg = tid & 3, pix = tid >> 2;
    int x = tx * 8 + (pix & 7);
    int y = ty * 8 + (pix >> 3);
    int p = y * 256 + x;
    float px = (x + 0.5f) / 128.0f - 1.0f;
    float py = 1.0f - (y + 0.5f) / 128.0f;

    unsigned long long bk = ((unsigned long long)__float_as_uint(HALF_BIGf)) << 32;
    float bw0 = 0.f, bw1 = 0.f;
    for (int j = seg; j < n; j += 4) {
        float4 Aj = sA[j];
        float4 Bj = sB[j];
        float2 zf = sZF[j];
        float w0 = fmaf(Aj.x, px, fmaf(Aj.y, py, Aj.z));
        float w1 = fmaf(Aj.w, px, fmaf(Bj.x, py, Bj.y));
        float z  = fmaf(Bj.z, px, fmaf(Bj.w, py, zf.x));
        float w2 = 1.0f - w0 - w1;                   // exact reference formula
        float m  = fminf(fminf(w0, w1), w2);
        // (zbits, fid) key: strict-min == jnp.argmin first-min tie-break
        unsigned long long k =
            (((unsigned long long)__float_as_uint(z)) << 32) | __float_as_uint(zf.y);
        bool take = (m >= 0.f) & (z > EPSf) & (k < bk);
        if (take) { bk = k; bw0 = w0; bw1 = w1; }
    }
    // quad merge: lanes 4k..4k+3 share a pixel
#pragma unroll
    for (int o = 1; o <= 2; o <<= 1) {
        unsigned long long ok = __shfl_xor_sync(0xffffffffu, bk, o);
        float ow0 = __shfl_xor_sync(0xffffffffu, bw0, o);
        float ow1 = __shfl_xor_sync(0xffffffffu, bw1, o);
        if (ok < bk) { bk = ok; bw0 = ow0; bw1 = ow1; }
    }

    // ---- epilogue: trilinear shade, 2 corners per quad lane ----
    float col0 = 0.f, col1 = 0.f, col2 = 0.f;
    if ((unsigned)(bk >> 32) < __float_as_uint(HALF_BIGf)) {
        int fw = (int)(unsigned)(bk & 0xFFFFFFFFu);
        float pw[3] = { bw0, bw1, 1.0f - bw0 - bw1 };
        int   i0c[3];
        float fr[3];
#pragma unroll
        for (int k = 0; k < 3; k++) {
            float u  = fminf(fmaxf(pw[k], 0.f), 1.f) * 3.0f;
            float fl = fminf(fmaxf(floorf(u), 0.f), 2.f);
            i0c[k] = (int)fl;
            fr[k] = u - fl;
        }
        const float* tb = tex + fw * 192;
#pragma unroll
        for (int q = 0; q < 2; q++) {
            int corner = seg * 2 + q;                // 8 corners split over quad
            int a = corner >> 2, bb = (corner >> 1) & 1, cc = corner & 1;
            float wc = (a  ? fr[0] : 1.f - fr[0])
                     * (bb ? fr[1] : 1.f - fr[1])
                     * (cc ? fr[2] : 1.f - fr[2]);
            int idx = ((i0c[0] + a) * 16 + (i0c[1] + bb) * 4 + (i0c[2] + cc)) * 3;
            col0 += wc * tanh_mufu(__ldg(tb + idx + 0));
            col1 += wc * tanh_mufu(__ldg(tb + idx + 1));
            col2 += wc * tanh_mufu(__ldg(tb + idx + 2));
        }
    }
#pragma unroll
    for (int o = 1; o <= 2; o <<= 1) {               // fixed butterfly: deterministic
        col0 += __shfl_xor_sync(0xffffffffu, col0, o);
        col1 += __shfl_xor_sync(0xffffffffu, col1, o);
        col2 += __shfl_xor_sync(0xffffffffu, col2, o);
    }

    double sum = 0.0;
    if (seg == 0) {
        float d0 = col0 - ref[p];
        float d1 = col1 - ref[65536 + p];
        float d2 = col2 - ref[131072 + p];
        sum = (double)d0 * d0 + (double)d1 * d1 + (double)d2 * d2;
    }
    int w = tid >> 5, lane = tid & 31;
#pragma unroll
    for (int o = 16; o; o >>= 1) sum += __shfl_down_sync(0xffffffffu, sum, o);
    if (lane == 0) ss[w] = sum;
    __syncthreads();
    if (tid == 0) {
        double t = 0.0;
        for (int i = 0; i < 8; i++) t += ss[i];
        g_partial[b] = t;
        __threadfence();                             // release g_partial
        unsigned old = atomicAdd(&g_rcount, 1u);
        sflag = ((old & (NTILE - 1)) == NTILE - 1);  // last block (monotonic: replay-safe)
        if (sflag) __threadfence();                  // acquire
    }
    __syncthreads();
    if (sflag) {                                     // fixed-order deterministic final reduce
        double v = __ldcg(&g_partial[tid])
                 + __ldcg(&g_partial[tid + 256])
                 + __ldcg(&g_partial[tid + 512])
                 + __ldcg(&g_partial[tid + 768]);
#pragma unroll
        for (int o = 16; o; o >>= 1) v += __shfl_down_sync(0xffffffffu, v, o);
        if (lane == 0) ss[w] = v;
        __syncthreads();
        if (tid == 0) {
            double t = 0.0;
            for (int i = 0; i < 8; i++) t += ss[i];
            out[0] = (float)t;
        }
    }
}

extern "C" void kernel_launch(void* const* d_in, const int* in_sizes, int n_in,
                              void* d_out, int out_size) {
    const float* verts = (const float*)d_in[0];   // (1,322,3)
    const int*   faces = (const int*)  d_in[1];   // (1,640,3)
    const float* tex   = (const float*)d_in[2];   // (1,640,4,4,4,3)
    const float* ref   = (const float*)d_in[3];   // (1,3,256,256)
    const float* angle = (const float*)d_in[4];   // (1,)

    fused_kernel<<<NTILE, NTHR>>>(verts, faces, tex, ref, angle, (float*)d_out);
}